// round 14
// baseline (speedup 1.0000x reference)
#include <cuda_runtime.h>
#include <math.h>

// Problem constants (match reference)
#define BATCH   16384
#define CTX     8
#define NEGS    5
#define NROWS   (CTX + 1 + NEGS)   // 14 gathered rows per batch
#define DIM     128
#define ROWF4   (DIM / 4)          // 32 float4 per embedding row
#define WPB     8                  // warps per block
#define TPB     (WPB * 32)
#define NBLOCKS 592                // 148 SMs x 4 CTAs: one balanced wave
#define TOTAL_WARPS (NBLOCKS * WPB)          // 4736
#define HEAVY   (BATCH - 3 * TOTAL_WARPS)    // 2176 warps take 4 batches

// SoA partials: g_part[k][block], k in {0..5}: [0]=s_pos, [1..5]=s_neg[n]
__device__ float g_part[6][NBLOCKS];
__device__ unsigned int g_ticket;   // zero-init; finalizing block resets it

__device__ __forceinline__ float log_sigmoid(float x) {
    return (x >= 0.0f) ? -log1pf(expf(-x)) : (x - log1pf(expf(x)));
}

// Fully-unrolled N-batch body: ptxas batches all N*14 row loads for max MLP.
// No predication, no loop guard — identical schedule quality to the R10 winner.
template<int N>
__device__ __forceinline__ void do_batches(
    int start, int lane,
    const int* __restrict__ pos_u,
    const int* __restrict__ pos_w,
    const int* __restrict__ neg_w,
    const float4* __restrict__ Wv,
    float acc[6])
{
#pragma unroll
    for (int it = 0; it < N; it++) {
        const int b = start + it;

        // Lanes 0..7: context idx; lane 8: positive; lanes 9..13: negatives.
        int idx = 0;
        if (lane < CTX)                 idx = pos_u[b * CTX + lane];
        else if (lane == CTX)           idx = pos_w[b];
        else if (lane < NROWS)          idx = neg_w[b * NEGS + (lane - CTX - 1)];

        // All 14 row loads issued up front. .cg: no L1 alloc (cross-SM touch
        // pattern -> ~0 L1 reuse; measured R2 vs R5).
        float4 r[NROWS];
#pragma unroll
        for (int t = 0; t < NROWS; t++) {
            int row = __shfl_sync(0xffffffffu, idx, t);
            r[t] = __ldcg(&Wv[(size_t)row * ROWF4 + lane]);
        }

        // Context sum (rows 0..7).
        float4 us = r[0];
#pragma unroll
        for (int c = 1; c < CTX; c++) {
            us.x += r[c].x; us.y += r[c].y; us.z += r[c].z; us.w += r[c].w;
        }

        // 6 dots: target rows 8..13 against Usum.
#pragma unroll
        for (int t = 0; t < 6; t++) {
            const float4 v = r[CTX + t];
            acc[t] += us.x * v.x + us.y * v.y + us.z * v.z + us.w * v.w;
        }
    }
}

__global__ __launch_bounds__(TPB, 4) void cbow_fused_kernel(
    const int* __restrict__ pos_u,   // [B, C]
    const int* __restrict__ pos_w,   // [B]
    const int* __restrict__ neg_w,   // [B, N]
    const float4* __restrict__ Wv,   // [VOCAB, 32] as float4
    float* __restrict__ out)
{
    const int lane = threadIdx.x & 31;
    const int wid  = threadIdx.x >> 5;
    const int gw   = blockIdx.x * WPB + wid;   // global warp id

    float acc[6];
#pragma unroll
    for (int k = 0; k < 6; k++) acc[k] = 0.0f;

    // Contiguous batch ranges: first HEAVY warps take 4 batches, rest take 3.
    // Warp-uniform branch between two statically-unrolled paths — zero
    // per-slot overhead, balanced per-SM work (max ~112 batches vs 128).
    if (gw < HEAVY) {
        do_batches<4>(gw * 4, lane, pos_u, pos_w, neg_w, Wv, acc);
    } else {
        do_batches<3>(HEAVY * 4 + (gw - HEAVY) * 3, lane,
                      pos_u, pos_w, neg_w, Wv, acc);
    }

    // Warp reduction of the 6 accumulated partials.
#pragma unroll
    for (int t = 0; t < 6; t++) {
        float v = acc[t];
#pragma unroll
        for (int o = 16; o > 0; o >>= 1)
            v += __shfl_xor_sync(0xffffffffu, v, o);
        acc[t] = v;
    }

    __shared__ float smem[6][WPB];
    __shared__ bool  s_last;
    if (lane == 0) {
#pragma unroll
        for (int t = 0; t < 6; t++) smem[t][wid] = acc[t];
    }
    __syncthreads();

    // Thread 0 publishes all 6 block partials (st.cg -> L2), then
    // release-orders them with an acq_rel ticket atomic. No __threadfence():
    // gpu-scope fence emits CCTL.IVALL (L1 wipe — the R3 regression).
    if (threadIdx.x == 0) {
        unsigned int mine;
#pragma unroll
        for (int k = 0; k < 6; k++) {
            float s = 0.0f;
#pragma unroll
            for (int i = 0; i < WPB; i++) s += smem[k][i];
            __stcg(&g_part[k][blockIdx.x], s);
        }
        asm volatile("atom.acq_rel.gpu.global.add.u32 %0, [%1], %2;"
                     : "=r"(mine) : "l"(&g_ticket), "r"(1u) : "memory");
        s_last = (mine == NBLOCKS - 1);
    }
    __syncthreads();

    if (s_last) {
        // Reduce 6 x 592 L2-resident partials (ldcg: L2-direct reads).
        const int t = threadIdx.x;
        float s[6];
#pragma unroll
        for (int k = 0; k < 6; k++) s[k] = 0.0f;
        for (int i = t; i < NBLOCKS; i += TPB) {
#pragma unroll
            for (int k = 0; k < 6; k++) s[k] += __ldcg(&g_part[k][i]);
        }
#pragma unroll
        for (int k = 0; k < 6; k++) {
#pragma unroll
            for (int o = 16; o > 0; o >>= 1)
                s[k] += __shfl_xor_sync(0xffffffffu, s[k], o);
        }
        __shared__ float fin[6][WPB];
        if (lane == 0) {
#pragma unroll
            for (int k = 0; k < 6; k++) fin[k][wid] = s[k];
        }
        __syncthreads();
        if (t == 0) {
            float tot[6];
#pragma unroll
            for (int k = 0; k < 6; k++) {
                float a = 0.0f;
#pragma unroll
                for (int i = 0; i < WPB; i++) a += fin[k][i];
                tot[k] = a;
            }
            float loss = -log_sigmoid(tot[0]);            // loss1
#pragma unroll
            for (int n = 0; n < NEGS; n++)
                loss -= log_sigmoid(-tot[1 + n]);         // - loss2
            out[0] = loss;
            g_ticket = 0;                                  // reset for next replay
        }
    }
}

extern "C" void kernel_launch(void* const* d_in, const int* in_sizes, int n_in,
                              void* d_out, int out_size) {
    const int*    pos_u = (const int*)d_in[0];
    const int*    pos_w = (const int*)d_in[1];
    const int*    neg_w = (const int*)d_in[2];
    const float4* Wv    = (const float4*)d_in[3];
    float*        out   = (float*)d_out;

    (void)in_sizes; (void)n_in; (void)out_size;

    cbow_fused_kernel<<<NBLOCKS, TPB>>>(pos_u, pos_w, neg_w, Wv, out);
}

// round 15
// speedup vs baseline: 1.0019x; 1.0019x over previous
#include <cuda_runtime.h>
#include <math.h>

// Problem constants (match reference)
#define BATCH   16384
#define CTX     8
#define NEGS    5
#define NROWS   (CTX + 1 + NEGS)   // 14 gathered rows per batch
#define DIM     128
#define ROWF4   (DIM / 4)          // 32 float4 per embedding row
#define WPB     8                  // warps per block
#define TPB     (WPB * 32)
#define NBLOCKS 1024               // 148 SMs: ~6.9 blocks/SM, short blocks
#define ITERS   (BATCH / (NBLOCKS * WPB))   // 2 batch-groups per block

// SoA partials: g_part[k][block], k in {0..5}: [0]=s_pos, [1..5]=s_neg[n]
__device__ float g_part[6][NBLOCKS];
__device__ unsigned int g_ticket;   // zero-init; finalizing block resets it

__device__ __forceinline__ float log_sigmoid(float x) {
    return (x >= 0.0f) ? -log1pf(expf(-x)) : (x - log1pf(expf(x)));
}

__global__ __launch_bounds__(TPB, 4) void cbow_fused_kernel(
    const int* __restrict__ pos_u,   // [B, C]
    const int* __restrict__ pos_w,   // [B]
    const int* __restrict__ neg_w,   // [B, N]
    const float4* __restrict__ Wv,   // [VOCAB, 32] as float4
    float* __restrict__ out)
{
    const int lane = threadIdx.x & 31;
    const int wid  = threadIdx.x >> 5;

    // Per-thread loss partials accumulated across ITERS batch-groups.
    float acc[6];
#pragma unroll
    for (int k = 0; k < 6; k++) acc[k] = 0.0f;

#pragma unroll
    for (int it = 0; it < ITERS; it++) {
        const int b = (it * NBLOCKS + blockIdx.x) * WPB + wid;  // batch id

        // Lanes 0..7: context idx; lane 8: positive; lanes 9..13: negatives.
        int idx = 0;
        if (lane < CTX)                 idx = pos_u[b * CTX + lane];
        else if (lane == CTX)           idx = pos_w[b];
        else if (lane < NROWS)          idx = neg_w[b * NEGS + (lane - CTX - 1)];

        // Issue ALL 14 row loads up front (max MLP). .cg: no L1 alloc
        // (cross-SM touch pattern -> ~0 L1 reuse; measured R2 vs R5).
        float4 r[NROWS];
#pragma unroll
        for (int t = 0; t < NROWS; t++) {
            int row = __shfl_sync(0xffffffffu, idx, t);
            r[t] = __ldcg(&Wv[(size_t)row * ROWF4 + lane]);
        }

        // Context sum (rows 0..7).
        float4 us = r[0];
#pragma unroll
        for (int c = 1; c < CTX; c++) {
            us.x += r[c].x; us.y += r[c].y; us.z += r[c].z; us.w += r[c].w;
        }

        // 6 dots: target rows 8..13 against Usum; accumulate across iters.
#pragma unroll
        for (int t = 0; t < 6; t++) {
            const float4 v = r[CTX + t];
            acc[t] += us.x * v.x + us.y * v.y + us.z * v.z + us.w * v.w;
        }
    }

    // Warp reduction of the 6 accumulated partials.
#pragma unroll
    for (int t = 0; t < 6; t++) {
        float v = acc[t];
#pragma unroll
        for (int o = 16; o > 0; o >>= 1)
            v += __shfl_xor_sync(0xffffffffu, v, o);
        acc[t] = v;
    }

    __shared__ float smem[6][WPB];
    __shared__ bool  s_last;
    if (lane == 0) {
#pragma unroll
        for (int t = 0; t < 6; t++) smem[t][wid] = acc[t];
    }
    __syncthreads();

    // Thread 0 publishes all 6 block partials (st.cg -> L2), then
    // release-orders them with an acq_rel ticket atomic. No __threadfence():
    // gpu-scope fence emits CCTL.IVALL (L1 wipe — the R3 regression).
    if (threadIdx.x == 0) {
        unsigned int mine;
#pragma unroll
        for (int k = 0; k < 6; k++) {
            float s = 0.0f;
#pragma unroll
            for (int i = 0; i < WPB; i++) s += smem[k][i];
            __stcg(&g_part[k][blockIdx.x], s);
        }
        asm volatile("atom.acq_rel.gpu.global.add.u32 %0, [%1], %2;"
                     : "=r"(mine) : "l"(&g_ticket), "r"(1u) : "memory");
        s_last = (mine == NBLOCKS - 1);
    }
    __syncthreads();

    if (s_last) {
        // Reduce 6 x 1024 L2-resident partials (ldcg: L2-direct reads).
        const int t = threadIdx.x;
        float s[6];
#pragma unroll
        for (int k = 0; k < 6; k++) s[k] = 0.0f;
#pragma unroll
        for (int j = 0; j < NBLOCKS / TPB; j++) {   // 4 coalesced iters
            int i = j * TPB + t;
#pragma unroll
            for (int k = 0; k < 6; k++) s[k] += __ldcg(&g_part[k][i]);
        }
#pragma unroll
        for (int k = 0; k < 6; k++) {
#pragma unroll
            for (int o = 16; o > 0; o >>= 1)
                s[k] += __shfl_xor_sync(0xffffffffu, s[k], o);
        }
        __shared__ float fin[6][WPB];
        if (lane == 0) {
#pragma unroll
            for (int k = 0; k < 6; k++) fin[k][wid] = s[k];
        }
        __syncthreads();
        if (t == 0) {
            float tot[6];
#pragma unroll
            for (int k = 0; k < 6; k++) {
                float a = 0.0f;
#pragma unroll
                for (int i = 0; i < WPB; i++) a += fin[k][i];
                tot[k] = a;
            }
            float loss = -log_sigmoid(tot[0]);            // loss1
#pragma unroll
            for (int n = 0; n < NEGS; n++)
                loss -= log_sigmoid(-tot[1 + n]);         // - loss2
            out[0] = loss;
            g_ticket = 0;                                  // reset for next replay
        }
    }
}

extern "C" void kernel_launch(void* const* d_in, const int* in_sizes, int n_in,
                              void* d_out, int out_size) {
    const int*    pos_u = (const int*)d_in[0];
    const int*    pos_w = (const int*)d_in[1];
    const int*    neg_w = (const int*)d_in[2];
    const float4* Wv    = (const float4*)d_in[3];
    float*        out   = (float*)d_out;

    (void)in_sizes; (void)n_in; (void)out_size;

    cbow_fused_kernel<<<NBLOCKS, TPB>>>(pos_u, pos_w, neg_w, Wv, out);
}

// round 16
// speedup vs baseline: 1.1616x; 1.1594x over previous
#include <cuda_runtime.h>
#include <math.h>

// Problem constants (match reference)
#define BATCH   16384
#define CTX     8
#define NEGS    5
#define NROWS   (CTX + 1 + NEGS)   // 14 gathered rows per batch
#define DIM     128
#define ROWF4   (DIM / 4)          // 32 float4 per embedding row
#define WPB     4                  // warps per block (finer placement quantum)
#define TPB     (WPB * 32)         // 128 threads
#define NBLOCKS 1024               // 148 SMs x ~7 blocks; 7v6 = 1.17x imbalance
#define ITERS   (BATCH / (NBLOCKS * WPB))   // 4 batch-groups per warp (winning unroll)

// SoA partials: g_part[k][block], k in {0..5}: [0]=s_pos, [1..5]=s_neg[n]
__device__ float g_part[6][NBLOCKS];
__device__ unsigned int g_ticket;   // zero-init; finalizing block resets it

__device__ __forceinline__ float log_sigmoid(float x) {
    return (x >= 0.0f) ? -log1pf(expf(-x)) : (x - log1pf(expf(x)));
}

__global__ __launch_bounds__(TPB, 8) void cbow_fused_kernel(
    const int* __restrict__ pos_u,   // [B, C]
    const int* __restrict__ pos_w,   // [B]
    const int* __restrict__ neg_w,   // [B, N]
    const float4* __restrict__ Wv,   // [VOCAB, 32] as float4
    float* __restrict__ out)
{
    const int lane = threadIdx.x & 31;
    const int wid  = threadIdx.x >> 5;

    // Per-thread loss partials accumulated across ITERS batch-groups.
    float acc[6];
#pragma unroll
    for (int k = 0; k < 6; k++) acc[k] = 0.0f;

#pragma unroll
    for (int it = 0; it < ITERS; it++) {
        const int b = (it * NBLOCKS + blockIdx.x) * WPB + wid;  // batch id

        // Lanes 0..7: context idx; lane 8: positive; lanes 9..13: negatives.
        int idx = 0;
        if (lane < CTX)                 idx = pos_u[b * CTX + lane];
        else if (lane == CTX)           idx = pos_w[b];
        else if (lane < NROWS)          idx = neg_w[b * NEGS + (lane - CTX - 1)];

        // Issue ALL 14 row loads up front (max MLP). .cg: no L1 alloc
        // (cross-SM touch pattern -> ~0 L1 reuse; measured R2 vs R5).
        float4 r[NROWS];
#pragma unroll
        for (int t = 0; t < NROWS; t++) {
            int row = __shfl_sync(0xffffffffu, idx, t);
            r[t] = __ldcg(&Wv[(size_t)row * ROWF4 + lane]);
        }

        // Context sum (rows 0..7).
        float4 us = r[0];
#pragma unroll
        for (int c = 1; c < CTX; c++) {
            us.x += r[c].x; us.y += r[c].y; us.z += r[c].z; us.w += r[c].w;
        }

        // 6 dots: target rows 8..13 against Usum; accumulate across iters.
#pragma unroll
        for (int t = 0; t < 6; t++) {
            const float4 v = r[CTX + t];
            acc[t] += us.x * v.x + us.y * v.y + us.z * v.z + us.w * v.w;
        }
    }

    // Warp reduction of the 6 accumulated partials.
#pragma unroll
    for (int t = 0; t < 6; t++) {
        float v = acc[t];
#pragma unroll
        for (int o = 16; o > 0; o >>= 1)
            v += __shfl_xor_sync(0xffffffffu, v, o);
        acc[t] = v;
    }

    __shared__ float smem[6][WPB];
    __shared__ bool  s_last;
    if (lane == 0) {
#pragma unroll
        for (int t = 0; t < 6; t++) smem[t][wid] = acc[t];
    }
    __syncthreads();

    // Thread 0 publishes all 6 block partials (st.cg -> L2), then
    // release-orders them with an acq_rel ticket atomic. No __threadfence():
    // gpu-scope fence emits CCTL.IVALL (L1 wipe — the R3 regression).
    if (threadIdx.x == 0) {
        unsigned int mine;
#pragma unroll
        for (int k = 0; k < 6; k++) {
            float s = 0.0f;
#pragma unroll
            for (int i = 0; i < WPB; i++) s += smem[k][i];
            __stcg(&g_part[k][blockIdx.x], s);
        }
        asm volatile("atom.acq_rel.gpu.global.add.u32 %0, [%1], %2;"
                     : "=r"(mine) : "l"(&g_ticket), "r"(1u) : "memory");
        s_last = (mine == NBLOCKS - 1);
    }
    __syncthreads();

    if (s_last) {
        // Reduce 6 x 1024 L2-resident partials (ldcg: L2-direct reads).
        const int t = threadIdx.x;
        float s[6];
#pragma unroll
        for (int k = 0; k < 6; k++) s[k] = 0.0f;
#pragma unroll
        for (int j = 0; j < NBLOCKS / TPB; j++) {   // 8 coalesced iters
            int i = j * TPB + t;
#pragma unroll
            for (int k = 0; k < 6; k++) s[k] += __ldcg(&g_part[k][i]);
        }
#pragma unroll
        for (int k = 0; k < 6; k++) {
#pragma unroll
            for (int o = 16; o > 0; o >>= 1)
                s[k] += __shfl_xor_sync(0xffffffffu, s[k], o);
        }
        __shared__ float fin[6][WPB];
        if (lane == 0) {
#pragma unroll
            for (int k = 0; k < 6; k++) fin[k][wid] = s[k];
        }
        __syncthreads();
        if (t == 0) {
            float tot[6];
#pragma unroll
            for (int k = 0; k < 6; k++) {
                float a = 0.0f;
#pragma unroll
                for (int i = 0; i < WPB; i++) a += fin[k][i];
                tot[k] = a;
            }
            float loss = -log_sigmoid(tot[0]);            // loss1
#pragma unroll
            for (int n = 0; n < NEGS; n++)
                loss -= log_sigmoid(-tot[1 + n]);         // - loss2
            out[0] = loss;
            g_ticket = 0;                                  // reset for next replay
        }
    }
}

extern "C" void kernel_launch(void* const* d_in, const int* in_sizes, int n_in,
                              void* d_out, int out_size) {
    const int*    pos_u = (const int*)d_in[0];
    const int*    pos_w = (const int*)d_in[1];
    const int*    neg_w = (const int*)d_in[2];
    const float4* Wv    = (const float4*)d_in[3];
    float*        out   = (float*)d_out;

    (void)in_sizes; (void)n_in; (void)out_size;

    cbow_fused_kernel<<<NBLOCKS, TPB>>>(pos_u, pos_w, neg_w, Wv, out);
}